// round 13
// baseline (speedup 1.0000x reference)
#include <cuda_runtime.h>
#include <cuda_bf16.h>
#include <cstdint>

// Problem constants (shape-fixed problem)
#define BB 2
#define LL 1024
#define D_SEQ 21
#define D_EMB 64
#define D_MODEL 128
#define ROWS (BB * LL)           // 2048

// Per-symbol separable tables (seq values are in [0, 21)).
__device__ float4 g_TP[D_SEQ * (D_MODEL / 4)];   // T_P[s,d] = bias[d] + sum_c emb[s,c]*W[d,c]
__device__ float4 g_TQ[D_SEQ * (D_MODEL / 4)];   // T_Q[s,d] = sum_c emb[s,c]*W[d,64+c]
__device__ float4 g_W128[D_MODEL / 4];           // packed W[:,128] column

// ---------------------------------------------------------------------------
// Kernel 1: per-symbol table precompute. 21 blocks x 128 threads.
// ---------------------------------------------------------------------------
__global__ __launch_bounds__(128) void table_kernel(
    const float* __restrict__ emb,     // [21, 64]
    const float* __restrict__ W,       // [128, 129] row-major
    const float* __restrict__ bias)    // [128]
{
    const int s = blockIdx.x;          // symbol 0..20
    const int d = threadIdx.x;         // 0..127

    __shared__ float e[D_EMB];
    if (d < D_EMB) e[d] = emb[s * D_EMB + d];
    __syncthreads();

    const float* wrow = W + d * 129;
    float accP = bias[d];
    float accQ = 0.0f;
#pragma unroll
    for (int c = 0; c < D_EMB; c++) {
        accP = fmaf(e[c], wrow[c], accP);
        accQ = fmaf(e[c], wrow[D_EMB + c], accQ);
    }
    ((float*)g_TP)[s * D_MODEL + d] = accP;
    ((float*)g_TQ)[s * D_MODEL + d] = accQ;
    if (s == 0) ((float*)g_W128)[d] = wrow[2 * D_EMB];   // W[d, 128]
}

// ---------------------------------------------------------------------------
// Kernel 2: out[b,i,j,d] = T_P[seq_i,d] + T_Q[seq_j,d] + log(|idx_i-idx_j|+1)*W128[d]
// Eighth-row blocks: grid = ROWS*8; block (rowi, chunk) owns j in
// [chunk*128, chunk*128+128). 256 threads = 8 warps; warp w owns 16 j's;
// lane t owns float4 d = 4t..4t+3. Hot loop identical to the measured best
// (R12: 147.0us @ NCHUNK=4, DRAM 87%). Finer ~8.5us blocks further shrink
// the partial-wave / completion-stagger DRAM idle.
// ---------------------------------------------------------------------------
#define NWARP 8
#define NCHUNK 8
#define JPB (LL / NCHUNK)       // 128 j's per block
#define JPW (JPB / NWARP)       // 16 j's per warp

__global__ __launch_bounds__(256) void pair_kernel(
    const int* __restrict__ seq,
    const int* __restrict__ idx,
    float4* __restrict__ out)
{
    const int blk = blockIdx.x;
    const int rowi = blk >> 3;              // b*L + i
    const int chunk = blk & (NCHUNK - 1);
    const int b = rowi >> 10;
    const int w = threadIdx.x >> 5;
    const int t = threadIdx.x & 31;

    // Setup (reads inputs only).
    const int idx_i = __ldg(idx + rowi);
    const int si = __ldg(seq + rowi);
    const int* __restrict__ idxb = idx + b * LL;
    const int* __restrict__ seqb = seq + b * LL;
    float4* __restrict__ outb = out + (size_t)rowi * LL * 32;

    __shared__ float4 sQ[D_SEQ * 32];       // 10.75 KB
    for (int k = threadIdx.x; k < D_SEQ * 32; k += 256) sQ[k] = __ldg(&g_TQ[k]);
    __syncthreads();

    const float4 p4 = __ldg(&g_TP[si * 32 + t]);
    const float4 w4 = __ldg(&g_W128[t]);

    const int j0 = chunk * JPB + w * JPW;
#pragma unroll 4
    for (int k = 0; k < JPW; k++) {
        const int j = j0 + k;
        const int sj = __ldg(seqb + j);
        const int idx_j = __ldg(idxb + j);
        const float s = __logf(fabsf((float)(idx_i - idx_j)) + 1.0f);
        const float4 q = sQ[sj * 32 + t];
        float4 o;
        o.x = fmaf(s, w4.x, p4.x + q.x);
        o.y = fmaf(s, w4.y, p4.y + q.y);
        o.z = fmaf(s, w4.z, p4.z + q.z);
        o.w = fmaf(s, w4.w, p4.w + q.w);
        __stcs(&outb[(size_t)j * 32 + t], o);
    }
}

// ---------------------------------------------------------------------------
// Launch: inputs per metadata order: seq(int32), idx(int32), emb_table(f32),
// W(f32 [128,129]), b(f32 [128]). Output: f32 [2,1024,1024,128].
// ---------------------------------------------------------------------------
extern "C" void kernel_launch(void* const* d_in, const int* in_sizes, int n_in,
                              void* d_out, int out_size)
{
    const int*   seq  = (const int*)d_in[0];
    const int*   idx  = (const int*)d_in[1];
    const float* emb  = (const float*)d_in[2];
    const float* W    = (const float*)d_in[3];
    const float* bias = (const float*)d_in[4];
    float4* out = (float4*)d_out;

    table_kernel<<<D_SEQ, 128>>>(emb, W, bias);
    pair_kernel<<<ROWS * NCHUNK, 256>>>(seq, idx, out);
}

// round 14
// speedup vs baseline: 1.4413x; 1.4413x over previous
#include <cuda_runtime.h>
#include <cuda_bf16.h>
#include <cstdint>

// Problem constants (shape-fixed problem)
#define BB 2
#define LL 1024
#define D_SEQ 21
#define D_EMB 64
#define D_MODEL 128
#define ROWS (BB * LL)           // 2048

// Per-symbol separable tables (seq values are in [0, 21)).
// g_TQ is only 10.75 KB -> L1-resident per SM via __ldg; no smem staging needed.
__device__ float4 g_TP[D_SEQ * (D_MODEL / 4)];   // T_P[s,d] = bias[d] + sum_c emb[s,c]*W[d,c]
__device__ float4 g_TQ[D_SEQ * (D_MODEL / 4)];   // T_Q[s,d] = sum_c emb[s,c]*W[d,64+c]
__device__ float4 g_W128[D_MODEL / 4];           // packed W[:,128] column

// ---------------------------------------------------------------------------
// Kernel 1: per-symbol table precompute. 21 blocks x 128 threads.
// ---------------------------------------------------------------------------
__global__ __launch_bounds__(128) void table_kernel(
    const float* __restrict__ emb,     // [21, 64]
    const float* __restrict__ W,       // [128, 129] row-major
    const float* __restrict__ bias)    // [128]
{
    const int s = blockIdx.x;          // symbol 0..20
    const int d = threadIdx.x;         // 0..127

    __shared__ float e[D_EMB];
    if (d < D_EMB) e[d] = emb[s * D_EMB + d];
    __syncthreads();

    const float* wrow = W + d * 129;
    float accP = bias[d];
    float accQ = 0.0f;
#pragma unroll
    for (int c = 0; c < D_EMB; c++) {
        accP = fmaf(e[c], wrow[c], accP);
        accQ = fmaf(e[c], wrow[D_EMB + c], accQ);
    }
    ((float*)g_TP)[s * D_MODEL + d] = accP;
    ((float*)g_TQ)[s * D_MODEL + d] = accQ;
    if (s == 0) ((float*)g_W128)[d] = wrow[2 * D_EMB];   // W[d, 128]
}

// ---------------------------------------------------------------------------
// Kernel 2: out[b,i,j,d] = T_P[seq_i,d] + T_Q[seq_j,d] + log(|idx_i-idx_j|+1)*W128[d]
// Eighth-row blocks (grid = ROWS*8, ~8.5us each) with ZERO prologue:
// Q comes straight from g_TQ via __ldg (10.75 KB table stays hot in each
// SM's L1 for the whole kernel). No smem, no staging loop, no __syncthreads
// -> fine blocks shrink the DRAM-idle tail (R12 lesson) without the
// prologue-amortization penalty that sank R13.
// 256 threads = 8 warps; warp w owns 16 j's; lane t owns float4 d=4t..4t+3.
// ---------------------------------------------------------------------------
#define NWARP 8
#define NCHUNK 8
#define JPB (LL / NCHUNK)       // 128 j's per block
#define JPW (JPB / NWARP)       // 16 j's per warp

__global__ __launch_bounds__(256) void pair_kernel(
    const int* __restrict__ seq,
    const int* __restrict__ idx,
    float4* __restrict__ out)
{
    const int blk = blockIdx.x;
    const int rowi = blk >> 3;              // b*L + i
    const int chunk = blk & (NCHUNK - 1);
    const int b = rowi >> 10;
    const int w = threadIdx.x >> 5;
    const int t = threadIdx.x & 31;

    const int idx_i = __ldg(idx + rowi);
    const int si = __ldg(seq + rowi);
    const int* __restrict__ idxb = idx + b * LL;
    const int* __restrict__ seqb = seq + b * LL;
    float4* __restrict__ outb = out + (size_t)rowi * LL * 32;

    const float4 p4 = __ldg(&g_TP[si * 32 + t]);
    const float4 w4 = __ldg(&g_W128[t]);

    const int j0 = chunk * JPB + w * JPW;
#pragma unroll 4
    for (int k = 0; k < JPW; k++) {
        const int j = j0 + k;
        const int sj = __ldg(seqb + j);
        const int idx_j = __ldg(idxb + j);
        const float s = __logf(fabsf((float)(idx_i - idx_j)) + 1.0f);
        const float4 q = __ldg(&g_TQ[sj * 32 + t]);   // L1-resident table
        float4 o;
        o.x = fmaf(s, w4.x, p4.x + q.x);
        o.y = fmaf(s, w4.y, p4.y + q.y);
        o.z = fmaf(s, w4.z, p4.z + q.z);
        o.w = fmaf(s, w4.w, p4.w + q.w);
        __stcs(&outb[(size_t)j * 32 + t], o);
    }
}

// ---------------------------------------------------------------------------
// Launch: inputs per metadata order: seq(int32), idx(int32), emb_table(f32),
// W(f32 [128,129]), b(f32 [128]). Output: f32 [2,1024,1024,128].
// ---------------------------------------------------------------------------
extern "C" void kernel_launch(void* const* d_in, const int* in_sizes, int n_in,
                              void* d_out, int out_size)
{
    const int*   seq  = (const int*)d_in[0];
    const int*   idx  = (const int*)d_in[1];
    const float* emb  = (const float*)d_in[2];
    const float* W    = (const float*)d_in[3];
    const float* bias = (const float*)d_in[4];
    float4* out = (float4*)d_out;

    table_kernel<<<D_SEQ, 128>>>(emb, W, bias);
    pair_kernel<<<ROWS * NCHUNK, 256>>>(seq, idx, out);
}

// round 15
// speedup vs baseline: 1.4498x; 1.0059x over previous
#include <cuda_runtime.h>
#include <cuda_bf16.h>
#include <cstdint>

// Problem constants (shape-fixed problem)
#define BB 2
#define LL 1024
#define D_SEQ 21
#define D_EMB 64
#define D_MODEL 128
#define ROWS (BB * LL)           // 2048

// Per-symbol separable tables (seq values are in [0, 21)).
// g_TQ is only 10.75 KB -> L1-resident per SM via __ldg; no smem staging needed.
__device__ float4 g_TP[D_SEQ * (D_MODEL / 4)];   // T_P[s,d] = bias[d] + sum_c emb[s,c]*W[d,c]
__device__ float4 g_TQ[D_SEQ * (D_MODEL / 4)];   // T_Q[s,d] = sum_c emb[s,c]*W[d,64+c]
__device__ float4 g_W128[D_MODEL / 4];           // packed W[:,128] column

// ---------------------------------------------------------------------------
// Kernel 1: per-symbol table precompute. 21 blocks x 128 threads.
// ---------------------------------------------------------------------------
__global__ __launch_bounds__(128) void table_kernel(
    const float* __restrict__ emb,     // [21, 64]
    const float* __restrict__ W,       // [128, 129] row-major
    const float* __restrict__ bias)    // [128]
{
    const int s = blockIdx.x;          // symbol 0..20
    const int d = threadIdx.x;         // 0..127

    __shared__ float e[D_EMB];
    if (d < D_EMB) e[d] = emb[s * D_EMB + d];
    __syncthreads();

    const float* wrow = W + d * 129;
    float accP = bias[d];
    float accQ = 0.0f;
#pragma unroll
    for (int c = 0; c < D_EMB; c++) {
        accP = fmaf(e[c], wrow[c], accP);
        accQ = fmaf(e[c], wrow[D_EMB + c], accQ);
    }
    ((float*)g_TP)[s * D_MODEL + d] = accP;
    ((float*)g_TQ)[s * D_MODEL + d] = accQ;
    if (s == 0) ((float*)g_W128)[d] = wrow[2 * D_EMB];   // W[d, 128]
}

// ---------------------------------------------------------------------------
// Kernel 2: out[b,i,j,d] = T_P[seq_i,d] + T_Q[seq_j,d] + log(|idx_i-idx_j|+1)*W128[d]
// Sixteenth-row blocks (grid = ROWS*16, ~4.3us each), ZERO prologue:
// Q comes straight from g_TQ via __ldg (10.75 KB table hot in each SM's L1).
// No smem, no staging, no __syncthreads — so finer work quanta shrink the
// partial-wave / completion-stagger DRAM idle at no amortization cost
// (R13 lesson: prologue cost * block count is what bites; here it's ~zero).
// 256 threads = 8 warps; warp w owns 8 j's; lane t owns float4 d=4t..4t+3.
// ---------------------------------------------------------------------------
#define NWARP 8
#define NCHUNK 16
#define JPB (LL / NCHUNK)       // 64 j's per block
#define JPW (JPB / NWARP)       // 8 j's per warp

__global__ __launch_bounds__(256) void pair_kernel(
    const int* __restrict__ seq,
    const int* __restrict__ idx,
    float4* __restrict__ out)
{
    const int blk = blockIdx.x;
    const int rowi = blk >> 4;              // b*L + i
    const int chunk = blk & (NCHUNK - 1);
    const int b = rowi >> 10;
    const int w = threadIdx.x >> 5;
    const int t = threadIdx.x & 31;

    const int idx_i = __ldg(idx + rowi);
    const int si = __ldg(seq + rowi);
    const int* __restrict__ idxb = idx + b * LL;
    const int* __restrict__ seqb = seq + b * LL;
    float4* __restrict__ outb = out + (size_t)rowi * LL * 32;

    const float4 p4 = __ldg(&g_TP[si * 32 + t]);
    const float4 w4 = __ldg(&g_W128[t]);

    const int j0 = chunk * JPB + w * JPW;
#pragma unroll 4
    for (int k = 0; k < JPW; k++) {
        const int j = j0 + k;
        const int sj = __ldg(seqb + j);
        const int idx_j = __ldg(idxb + j);
        const float s = __logf(fabsf((float)(idx_i - idx_j)) + 1.0f);
        const float4 q = __ldg(&g_TQ[sj * 32 + t]);   // L1-resident table
        float4 o;
        o.x = fmaf(s, w4.x, p4.x + q.x);
        o.y = fmaf(s, w4.y, p4.y + q.y);
        o.z = fmaf(s, w4.z, p4.z + q.z);
        o.w = fmaf(s, w4.w, p4.w + q.w);
        __stcs(&outb[(size_t)j * 32 + t], o);
    }
}

// ---------------------------------------------------------------------------
// Launch: inputs per metadata order: seq(int32), idx(int32), emb_table(f32),
// W(f32 [128,129]), b(f32 [128]). Output: f32 [2,1024,1024,128].
// ---------------------------------------------------------------------------
extern "C" void kernel_launch(void* const* d_in, const int* in_sizes, int n_in,
                              void* d_out, int out_size)
{
    const int*   seq  = (const int*)d_in[0];
    const int*   idx  = (const int*)d_in[1];
    const float* emb  = (const float*)d_in[2];
    const float* W    = (const float*)d_in[3];
    const float* bias = (const float*)d_in[4];
    float4* out = (float4*)d_out;

    table_kernel<<<D_SEQ, 128>>>(emb, W, bias);
    pair_kernel<<<ROWS * NCHUNK, 256>>>(seq, idx, out);
}